// round 5
// baseline (speedup 1.0000x reference)
#include <cuda_runtime.h>

#define C        1000
#define BATCH    64
#define SPLIT    4
#define THREADS  256
#define CHUNK    250            // C / SPLIT
#define NPART    (BATCH * SPLIT)

__device__ float g_partial[NPART];

__global__ void __launch_bounds__(THREADS)
distill_main(const float* __restrict__ y_s,
             const float* __restrict__ y_t,
             const float* __restrict__ w_in)
{
    __shared__ float s_xs[1024], s_xt[1024], s_w[1024];
    __shared__ float s_xsP[1024], s_xtP[1024];
    __shared__ float s_redA[8], s_redB[8];
    __shared__ int   s_wcnt[8], s_woff[8];
    __shared__ int   s_P;
    __shared__ float s_nsS, s_nsT;

    const int b    = blockIdx.x;
    const int tid  = threadIdx.x;
    const int lane = tid & 31;
    const int wid  = tid >> 5;

    const float* ysr = y_s  + b * C;
    const float* ytr = y_t  + b * C;
    const float* wr  = w_in + b * C;

    // ---- load row into shared (x = y / T, T = 4) ----
    for (int i = tid; i < 1024; i += THREADS) {
        if (i < C) {
            s_xs[i] = ysr[i] * 0.25f;
            s_xt[i] = ytr[i] * 0.25f;
            s_w[i]  = wr[i];
        } else {
            s_xs[i] = 0.0f; s_xt[i] = 0.0f; s_w[i] = 0.0f;
        }
    }
    __syncthreads();

    // ---- neg_sum = sum_k (1-w) * exp(x_k) for both matrices ----
    float ns_s = 0.0f, ns_t = 0.0f;
    for (int i = tid; i < C; i += THREADS) {
        float wv = s_w[i];
        float om = 1.0f - wv;
        ns_s += om * __expf(s_xs[i]);
        ns_t += om * __expf(s_xt[i]);
    }
    #pragma unroll
    for (int d = 16; d > 0; d >>= 1) {
        ns_s += __shfl_down_sync(0xffffffffu, ns_s, d);
        ns_t += __shfl_down_sync(0xffffffffu, ns_t, d);
    }
    if (lane == 0) { s_redA[wid] = ns_s; s_redB[wid] = ns_t; }

    // ---- deterministic order-preserving compaction of w==1 entries ----
    // Each thread owns 4 consecutive elements.
    const int base = tid * 4;
    unsigned m4 = 0; int cnt = 0;
    #pragma unroll
    for (int j = 0; j < 4; j++) {
        if (s_w[base + j] != 0.0f) { m4 |= (1u << j); cnt++; }
    }
    int incl = cnt;
    #pragma unroll
    for (int d = 1; d < 32; d <<= 1) {
        int v = __shfl_up_sync(0xffffffffu, incl, d);
        if (lane >= d) incl += v;
    }
    if (lane == 31) s_wcnt[wid] = incl;
    __syncthreads();
    if (tid == 0) {
        float a = 0.0f, bb = 0.0f; int run = 0;
        #pragma unroll
        for (int k2 = 0; k2 < 8; k2++) {
            a  += s_redA[k2];
            bb += s_redB[k2];
            s_woff[k2] = run;
            run += s_wcnt[k2];
        }
        s_nsS = a; s_nsT = bb; s_P = run;
    }
    __syncthreads();
    {
        int off = s_woff[wid] + (incl - cnt);
        #pragma unroll
        for (int j = 0; j < 4; j++) {
            if (m4 & (1u << j)) {
                s_xsP[off] = s_xs[base + j];
                s_xtP[off] = s_xt[base + j];
                off++;
            }
        }
    }
    __syncthreads();

    const int   P    = s_P;
    const float negS = s_nsS;
    const float negT = s_nsT;

    // ---- main O(C*P) loop: each thread handles one i in this block's slice ----
    float contrib = 0.0f;
    const int i = blockIdx.y * CHUNK + tid;
    if (tid < CHUNK && i < C) {
        const float xsi = s_xs[i];
        const float xti = s_xt[i];
        const float wi  = s_w[i];

        float accs = 0.0f, acct = 0.0f;
        #pragma unroll 4
        for (int k = 0; k < P; k++) {
            accs += fmaxf(xsi - s_xsP[k], 0.0f);
            acct += fmaxf(xti - s_xtP[k], 0.0f);
        }
        const float t3s = accs * (1.0f / (float)C);
        const float t3t = acct * (1.0f / (float)C);

        const float exs = __expf(xsi);
        const float ext = __expf(xti);
        const float chs = wi * __expf(-t3s) + (1.0f - wi);
        const float cht = wi * __expf(-t3t) + (1.0f - wi);

        const float ps = exs / (chs * negS + exs);
        const float pt = ext / (cht * negT + ext);

        const float ps1 = fminf(ps, 1.0f);
        const float pt1 = fminf(pt, 1.0f);

        const float da  = fminf(fabsf((pt1 + 1.0f) * 0.5f - ps1), 1.0f);
        const float pos = wi * sqrtf(sqrtf(da));
        const float neg = (1.0f - wi) * fminf(fabsf(pt1 * 0.5f - ps1), 1.0f);
        const float ept = pos + neg;

        float psE = __expf(ept * __logf(ps1));   // ps1^ept, ps1 in (0,1]
        psE = fmaxf(psE, 1e-7f);
        const float ptc = fmaxf(pt, 1e-7f);
        contrib = ptc * __logf(psE);
    }

    // ---- block reduction (fixed tree, deterministic) ----
    #pragma unroll
    for (int d = 16; d > 0; d >>= 1)
        contrib += __shfl_down_sync(0xffffffffu, contrib, d);
    if (lane == 0) s_redA[wid] = contrib;
    __syncthreads();
    if (tid == 0) {
        float t = 0.0f;
        #pragma unroll
        for (int k2 = 0; k2 < 8; k2++) t += s_redA[k2];
        g_partial[blockIdx.x * SPLIT + blockIdx.y] = t;
    }
}

__global__ void __launch_bounds__(THREADS)
distill_reduce(float* __restrict__ out, int out_size)
{
    __shared__ float s_red[8];
    const int tid  = threadIdx.x;
    const int lane = tid & 31;
    const int wid  = tid >> 5;

    float v = (tid < NPART) ? g_partial[tid] : 0.0f;
    #pragma unroll
    for (int d = 16; d > 0; d >>= 1)
        v += __shfl_down_sync(0xffffffffu, v, d);
    if (lane == 0) s_red[wid] = v;
    __syncthreads();
    if (tid == 0) {
        float t = 0.0f;
        #pragma unroll
        for (int k2 = 0; k2 < 8; k2++) t += s_red[k2];
        // loss = -(sum_{b,i} pt*log(ps)) / B * T^2 = -total * 16/64
        out[0] = -0.25f * t;
    }
    // any extra output elements -> zero
    for (int i = tid; i < out_size; i += THREADS)
        if (i > 0) out[i] = 0.0f;
}

extern "C" void kernel_launch(void* const* d_in, const int* in_sizes, int n_in,
                              void* d_out, int out_size)
{
    const float* y_s = (const float*)d_in[0];
    const float* y_t = (const float*)d_in[1];
    const float* w   = (const float*)d_in[2];

    dim3 grid(BATCH, SPLIT);
    distill_main<<<grid, THREADS>>>(y_s, y_t, w);
    distill_reduce<<<1, THREADS>>>((float*)d_out, out_size);
}

// round 10
// speedup vs baseline: 1.2786x; 1.2786x over previous
#include <cuda_runtime.h>

#define C        1000
#define BATCH    64
#define THREADS  256
#define QSCALE   1048576.0f              // 2^20
#define T3SCALE  9.5367431640625e-10f    // 2^-20 / 1000

__device__ float        g_partial[BATCH];
__device__ unsigned int g_count = 0;

// Monotone bucket map: quantized value -> [0,255]. Buckets of width 1/128 over [-1,1].
// Clamped edges remain exact: bucket() is monotone, so cross-bucket ordering is
// always consistent with value ordering; same-bucket pairs are resolved exactly
// by the integer scan.
__device__ __forceinline__ int bucket_of(int q) {
    int b = (q + (1 << 20)) >> 13;
    return min(max(b, 0), 255);
}

__global__ void __launch_bounds__(THREADS)
distill_fused(const float* __restrict__ y_s,
              const float* __restrict__ y_t,
              const float* __restrict__ w_in,
              float* __restrict__ out, int out_size)
{
    __shared__ float s_xs[C], s_xt[C], s_w[C];
    __shared__ int   h_cnt[2][256], h_sum[2][256];   // per-bucket count / int sum of keys
    __shared__ int   p_cnt[2][256], p_sum[2][256];   // exclusive prefixes
    __shared__ int   sc[2][256];                     // scatter counters
    __shared__ int   stg[2][1024];                   // bucket-grouped quantized keys
    __shared__ int   s_wt[8];
    __shared__ float s_redA[8], s_redB[8];
    __shared__ float s_ns[2];
    __shared__ float s_fin[2];
    __shared__ bool  s_isLast;

    const int b    = blockIdx.x;
    const int tid  = threadIdx.x;
    const int lane = tid & 31;
    const int wid  = tid >> 5;

    const float* ysr = y_s  + b * C;
    const float* ytr = y_t  + b * C;
    const float* wr  = w_in + b * C;

    // ---- load row (x = y / T, T = 4); zero histograms ----
    for (int i = tid; i < C; i += THREADS) {
        s_xs[i] = ysr[i] * 0.25f;
        s_xt[i] = ytr[i] * 0.25f;
        s_w[i]  = wr[i];
    }
    h_cnt[0][tid] = 0; h_cnt[1][tid] = 0;
    h_sum[0][tid] = 0; h_sum[1][tid] = 0;
    sc[0][tid]    = 0; sc[1][tid]    = 0;
    __syncthreads();

    // ---- neg_sum = sum_k (1-w)*exp(x_k), both matrices ----
    float ns_s = 0.0f, ns_t = 0.0f;
    for (int i = tid; i < C; i += THREADS) {
        float om = 1.0f - s_w[i];
        ns_s += om * __expf(s_xs[i]);
        ns_t += om * __expf(s_xt[i]);
    }
    #pragma unroll
    for (int d = 16; d > 0; d >>= 1) {
        ns_s += __shfl_down_sync(0xffffffffu, ns_s, d);
        ns_t += __shfl_down_sync(0xffffffffu, ns_t, d);
    }
    if (lane == 0) { s_redA[wid] = ns_s; s_redB[wid] = ns_t; }

    // ---- histogram build over w==1 keys (int atomics: exactly deterministic) ----
    const int kbase = tid * 4;
    #pragma unroll
    for (int j = 0; j < 4; j++) {
        int k = kbase + j;
        if (k < C && s_w[k] != 0.0f) {
            int q0 = __float2int_rn(s_xs[k] * QSCALE);
            int b0 = bucket_of(q0);
            atomicAdd(&h_cnt[0][b0], 1);
            atomicAdd(&h_sum[0][b0], q0);
            int q1 = __float2int_rn(s_xt[k] * QSCALE);
            int b1 = bucket_of(q1);
            atomicAdd(&h_cnt[1][b1], 1);
            atomicAdd(&h_sum[1][b1], q1);
        }
    }
    __syncthreads();

    if (tid == 0) {
        float a = 0.0f, bb = 0.0f;
        #pragma unroll
        for (int k2 = 0; k2 < 8; k2++) { a += s_redA[k2]; bb += s_redB[k2]; }
        s_ns[0] = a; s_ns[1] = bb;
    }

    // ---- exclusive prefix scans over 256 buckets (cnt & sum, both matrices) ----
    #pragma unroll
    for (int m = 0; m < 2; m++) {
        #pragma unroll
        for (int which = 0; which < 2; which++) {
            int v    = which ? h_sum[m][tid] : h_cnt[m][tid];
            int incl = v;
            #pragma unroll
            for (int d = 1; d < 32; d <<= 1) {
                int t = __shfl_up_sync(0xffffffffu, incl, d);
                if (lane >= d) incl += t;
            }
            if (lane == 31) s_wt[wid] = incl;
            __syncthreads();
            if (tid == 0) {
                int run = 0;
                #pragma unroll
                for (int k2 = 0; k2 < 8; k2++) { int t = s_wt[k2]; s_wt[k2] = run; run += t; }
            }
            __syncthreads();
            int r = s_wt[wid] + incl - v;
            if (which) p_sum[m][tid] = r; else p_cnt[m][tid] = r;
            __syncthreads();
        }
    }

    // ---- scatter keys bucket-grouped (order nondeterministic; values int => OK) ----
    #pragma unroll
    for (int j = 0; j < 4; j++) {
        int k = kbase + j;
        if (k < C && s_w[k] != 0.0f) {
            int q0 = __float2int_rn(s_xs[k] * QSCALE);
            int b0 = bucket_of(q0);
            stg[0][p_cnt[0][b0] + atomicAdd(&sc[0][b0], 1)] = q0;
            int q1 = __float2int_rn(s_xt[k] * QSCALE);
            int b1 = bucket_of(q1);
            stg[1][p_cnt[1][b1] + atomicAdd(&sc[1][b1], 1)] = q1;
        }
    }
    __syncthreads();

    const float negS = s_ns[0];
    const float negT = s_ns[1];

    // ---- queries: t3 via rank/sum lookup, then epilogue ----
    float contrib = 0.0f;
    for (int i = tid; i < C; i += THREADS) {
        const float xsi = s_xs[i];
        const float xti = s_xt[i];
        const float wi  = s_w[i];

        // matrix 0 (student)
        int qs = __float2int_rn(xsi * QSCALE);
        int bs = bucket_of(qs);
        int cs = p_cnt[0][bs];
        long long ss = p_sum[0][bs];
        {
            int st = p_cnt[0][bs], n = h_cnt[0][bs];
            for (int t = 0; t < n; t++) {
                int kq = stg[0][st + t];
                if (kq < qs) { cs++; ss += kq; }
            }
        }
        const float t3s = (float)((long long)cs * (long long)qs - ss) * T3SCALE;

        // matrix 1 (teacher)
        int qt = __float2int_rn(xti * QSCALE);
        int bt = bucket_of(qt);
        int ct = p_cnt[1][bt];
        long long st2 = p_sum[1][bt];
        {
            int st = p_cnt[1][bt], n = h_cnt[1][bt];
            for (int t = 0; t < n; t++) {
                int kq = stg[1][st + t];
                if (kq < qt) { ct++; st2 += kq; }
            }
        }
        const float t3t = (float)((long long)ct * (long long)qt - st2) * T3SCALE;

        // epilogue (identical math to the passing R1 kernel)
        const float exs = __expf(xsi);
        const float ext = __expf(xti);
        const float chs = wi * __expf(-t3s) + (1.0f - wi);
        const float cht = wi * __expf(-t3t) + (1.0f - wi);

        const float ps = exs / (chs * negS + exs);
        const float pt = ext / (cht * negT + ext);

        const float ps1 = fminf(ps, 1.0f);
        const float pt1 = fminf(pt, 1.0f);

        const float da  = fminf(fabsf((pt1 + 1.0f) * 0.5f - ps1), 1.0f);
        const float pos = wi * sqrtf(sqrtf(da));
        const float neg = (1.0f - wi) * fminf(fabsf(pt1 * 0.5f - ps1), 1.0f);
        const float ept = pos + neg;

        float psE = __expf(ept * __logf(ps1));
        psE = fmaxf(psE, 1e-7f);
        const float ptc = fmaxf(pt, 1e-7f);
        contrib += ptc * __logf(psE);
    }

    // ---- block reduction (fixed tree) ----
    #pragma unroll
    for (int d = 16; d > 0; d >>= 1)
        contrib += __shfl_down_sync(0xffffffffu, contrib, d);
    if (lane == 0) s_redA[wid] = contrib;
    __syncthreads();

    if (tid == 0) {
        float t = 0.0f;
        #pragma unroll
        for (int k2 = 0; k2 < 8; k2++) t += s_redA[k2];
        g_partial[b] = t;
        __threadfence();
        unsigned c = atomicAdd(&g_count, 1u);
        s_isLast = (c == (unsigned)(BATCH - 1));
    }
    __syncthreads();

    // ---- fused final reduce: last block sums fixed-order partials ----
    if (s_isLast) {
        float v = 0.0f;
        if (tid < BATCH) v = ((volatile float*)g_partial)[tid];
        #pragma unroll
        for (int d = 16; d > 0; d >>= 1)
            v += __shfl_down_sync(0xffffffffu, v, d);
        if (tid == 0)  s_fin[0] = v;
        if (tid == 32) s_fin[1] = v;
        __syncthreads();
        if (tid == 0) {
            // loss = -(total)/B * T^2 = -total * 16/64
            out[0] = -0.25f * (s_fin[0] + s_fin[1]);
            g_count = 0;   // reset for next graph replay
        }
        for (int i = tid; i < out_size; i += THREADS)
            if (i > 0) out[i] = 0.0f;
    }
}

extern "C" void kernel_launch(void* const* d_in, const int* in_sizes, int n_in,
                              void* d_out, int out_size)
{
    const float* y_s = (const float*)d_in[0];
    const float* y_t = (const float*)d_in[1];
    const float* w   = (const float*)d_in[2];

    distill_fused<<<BATCH, THREADS>>>(y_s, y_t, w, (float*)d_out, out_size);
}

// round 11
// speedup vs baseline: 1.4581x; 1.1404x over previous
#include <cuda_runtime.h>

#define C        1000
#define BATCH    64
#define THREADS  512
#define NB       512                     // buckets
#define QSCALE   1048576.0f              // 2^20
#define T3SCALE  9.5367431640625e-10f    // 2^-20 / 1000
#define KBIAS    (1 << 22)               // positivity bias for packed sums
#define M40      ((1ull << 40) - 1ull)

__device__ float        g_partial[BATCH];
__device__ unsigned int g_count = 0;

// Monotone bucket map: quantized value -> [0,511]. Width 2^12 quant units.
__device__ __forceinline__ int bucket_of(int q) {
    int b = (q + (1 << 20)) >> 12;
    return min(max(b, 0), NB - 1);
}

__global__ void __launch_bounds__(THREADS)
distill_fused(const float* __restrict__ y_s,
              const float* __restrict__ y_t,
              const float* __restrict__ w_in,
              float* __restrict__ out, int out_size)
{
    __shared__ float s_xs[C], s_xt[C], s_w[C];
    __shared__ unsigned long long s_h[2][NB];   // packed (cnt<<40) + sum(q+KBIAS)
    __shared__ unsigned long long s_p[2][NB];   // exclusive prefix of s_h
    __shared__ int   s_sc[2][NB];               // scatter counters
    __shared__ int   s_stg[2][1024];            // bucket-grouped quantized keys
    __shared__ unsigned long long s_wt64[16];
    __shared__ float s_redA[16], s_redB[16];
    __shared__ float s_ns[2];
    __shared__ float s_fin[2];
    __shared__ bool  s_isLast;

    const int b    = blockIdx.x;
    const int tid  = threadIdx.x;
    const int lane = tid & 31;
    const int wid  = tid >> 5;

    // ---- phase 1: vectorized load (x = y/4), zero histograms ----
    {
        const float4* ys4 = (const float4*)(y_s  + b * C);
        const float4* yt4 = (const float4*)(y_t  + b * C);
        const float4* w4  = (const float4*)(w_in + b * C);
        if (tid < C / 4) {
            float4 a = ys4[tid], c = yt4[tid], d = w4[tid];
            int o = tid * 4;
            s_xs[o+0] = a.x*0.25f; s_xs[o+1] = a.y*0.25f; s_xs[o+2] = a.z*0.25f; s_xs[o+3] = a.w*0.25f;
            s_xt[o+0] = c.x*0.25f; s_xt[o+1] = c.y*0.25f; s_xt[o+2] = c.z*0.25f; s_xt[o+3] = c.w*0.25f;
            s_w [o+0] = d.x;       s_w [o+1] = d.y;       s_w [o+2] = d.z;       s_w [o+3] = d.w;
        }
        s_h[0][tid] = 0ull; s_h[1][tid] = 0ull;
        s_sc[0][tid] = 0;   s_sc[1][tid] = 0;
    }
    __syncthreads();

    // ---- phase 2: neg_sum partials + packed histogram build ----
    float ns_s = 0.0f, ns_t = 0.0f;
    #pragma unroll
    for (int r = 0; r < 2; r++) {
        int i = tid + r * THREADS;
        if (i < C) {
            float wv = s_w[i];
            float om = 1.0f - wv;
            ns_s += om * __expf(s_xs[i]);
            ns_t += om * __expf(s_xt[i]);
            if (wv != 0.0f) {
                int q0 = __float2int_rn(s_xs[i] * QSCALE);
                atomicAdd(&s_h[0][bucket_of(q0)],
                          (1ull << 40) + (unsigned long long)(unsigned)(q0 + KBIAS));
                int q1 = __float2int_rn(s_xt[i] * QSCALE);
                atomicAdd(&s_h[1][bucket_of(q1)],
                          (1ull << 40) + (unsigned long long)(unsigned)(q1 + KBIAS));
            }
        }
    }
    #pragma unroll
    for (int d = 16; d > 0; d >>= 1) {
        ns_s += __shfl_down_sync(0xffffffffu, ns_s, d);
        ns_t += __shfl_down_sync(0xffffffffu, ns_t, d);
    }
    if (lane == 0) { s_redA[wid] = ns_s; s_redB[wid] = ns_t; }
    __syncthreads();

    // ---- phase 3: two concurrent exclusive scans (one per matrix, packed 64-bit) ----
    {
        const int m = tid >> 8;        // 0: student, 1: teacher
        const int t = tid & 255;       // 2 buckets per thread
        unsigned long long v0 = s_h[m][2*t], v1 = s_h[m][2*t+1];
        unsigned long long s  = v0 + v1;
        unsigned long long incl = s;
        #pragma unroll
        for (int d = 1; d < 32; d <<= 1) {
            unsigned long long u = __shfl_up_sync(0xffffffffu, incl, d);
            if (lane >= d) incl += u;
        }
        if (lane == 31) s_wt64[wid] = incl;
        __syncthreads();
        if (tid == 0) {
            unsigned long long run = 0;
            #pragma unroll
            for (int k = 0; k < 8; k++) { unsigned long long tt = s_wt64[k]; s_wt64[k] = run; run += tt; }
            // fold neg_sum combine into this serial slot
            float a = 0.0f, bb = 0.0f;
            #pragma unroll
            for (int k = 0; k < 16; k++) { a += s_redA[k]; bb += s_redB[k]; }
            s_ns[0] = a; s_ns[1] = bb;
        }
        if (tid == 256) {
            unsigned long long run = 0;
            #pragma unroll
            for (int k = 8; k < 16; k++) { unsigned long long tt = s_wt64[k]; s_wt64[k] = run; run += tt; }
        }
        __syncthreads();
        unsigned long long base = s_wt64[wid] + (incl - s);
        s_p[m][2*t]   = base;
        s_p[m][2*t+1] = base + v0;
    }
    __syncthreads();

    // ---- phase 4: scatter keys bucket-grouped (int values: order-independent) ----
    #pragma unroll
    for (int r = 0; r < 2; r++) {
        int k = tid + r * THREADS;
        if (k < C && s_w[k] != 0.0f) {
            int q0 = __float2int_rn(s_xs[k] * QSCALE);
            int b0 = bucket_of(q0);
            s_stg[0][(int)(s_p[0][b0] >> 40) + atomicAdd(&s_sc[0][b0], 1)] = q0;
            int q1 = __float2int_rn(s_xt[k] * QSCALE);
            int b1 = bucket_of(q1);
            s_stg[1][(int)(s_p[1][b1] >> 40) + atomicAdd(&s_sc[1][b1], 1)] = q1;
        }
    }
    __syncthreads();

    const float negS = s_ns[0];
    const float negT = s_ns[1];

    // ---- phase 5: queries (rank/sum lookup) + epilogue ----
    float contrib = 0.0f;
    #pragma unroll
    for (int r = 0; r < 2; r++) {
        int i = tid + r * THREADS;
        if (i < C) {
            const float xsi = s_xs[i];
            const float xti = s_xt[i];
            const float wi  = s_w[i];

            float t3[2];
            const float xv[2] = { xsi, xti };
            #pragma unroll
            for (int m = 0; m < 2; m++) {
                int q  = __float2int_rn(xv[m] * QSCALE);
                int bk = bucket_of(q);
                unsigned long long pk = s_p[m][bk];
                long long cnt = (long long)(pk >> 40);
                long long sum = (long long)(pk & M40) - (cnt << 22);
                int st = (int)(pk >> 40);
                int n  = (int)(s_h[m][bk] >> 40);
                for (int t = 0; t < n; t++) {
                    int kq = s_stg[m][st + t];
                    if (kq < q) { cnt++; sum += kq; }
                }
                t3[m] = (float)(cnt * (long long)q - sum) * T3SCALE;
            }

            const float exs = __expf(xsi);
            const float ext = __expf(xti);
            const float chs = wi * __expf(-t3[0]) + (1.0f - wi);
            const float cht = wi * __expf(-t3[1]) + (1.0f - wi);

            const float ps = exs / (chs * negS + exs);
            const float pt = ext / (cht * negT + ext);

            const float ps1 = fminf(ps, 1.0f);
            const float pt1 = fminf(pt, 1.0f);

            const float da  = fminf(fabsf((pt1 + 1.0f) * 0.5f - ps1), 1.0f);
            const float pos = wi * sqrtf(sqrtf(da));
            const float neg = (1.0f - wi) * fminf(fabsf(pt1 * 0.5f - ps1), 1.0f);
            const float ept = pos + neg;

            float psE = __expf(ept * __logf(ps1));
            psE = fmaxf(psE, 1e-7f);
            const float ptc = fmaxf(pt, 1e-7f);
            contrib += ptc * __logf(psE);
        }
    }

    // ---- phase 6: block reduction (fixed tree, deterministic) ----
    #pragma unroll
    for (int d = 16; d > 0; d >>= 1)
        contrib += __shfl_down_sync(0xffffffffu, contrib, d);
    if (lane == 0) s_redA[wid] = contrib;
    __syncthreads();

    if (tid == 0) {
        float t = 0.0f;
        #pragma unroll
        for (int k = 0; k < 16; k++) t += s_redA[k];
        g_partial[b] = t;
        __threadfence();
        unsigned c = atomicAdd(&g_count, 1u);
        s_isLast = (c == (unsigned)(BATCH - 1));
    }
    __syncthreads();

    // ---- phase 7: fused final reduce (last block, fixed order) ----
    if (s_isLast) {
        float v = 0.0f;
        if (tid < BATCH) v = ((volatile float*)g_partial)[tid];
        #pragma unroll
        for (int d = 16; d > 0; d >>= 1)
            v += __shfl_down_sync(0xffffffffu, v, d);
        if (tid == 0)  s_fin[0] = v;
        if (tid == 32) s_fin[1] = v;
        __syncthreads();
        if (tid == 0) {
            // loss = -(total)/B * T^2 = -total * 16/64
            out[0] = -0.25f * (s_fin[0] + s_fin[1]);
            g_count = 0;   // reset for next graph replay
        }
        for (int i = tid; i < out_size; i += THREADS)
            if (i > 0) out[i] = 0.0f;
    }
}

extern "C" void kernel_launch(void* const* d_in, const int* in_sizes, int n_in,
                              void* d_out, int out_size)
{
    const float* y_s = (const float*)d_in[0];
    const float* y_t = (const float*)d_in[1];
    const float* w   = (const float*)d_in[2];

    distill_fused<<<BATCH, THREADS>>>(y_s, y_t, w, (float*)d_out, out_size);
}

// round 12
// speedup vs baseline: 1.7725x; 1.2156x over previous
#include <cuda_runtime.h>

#define C        1000
#define BATCH    64
#define THREADS  1024
#define NB       512                     // buckets per matrix
#define QSCALE   1048576.0f              // 2^20
#define T3SCALE  9.5367431640625e-10f    // 2^-20 / 1000
#define KBIAS    (1 << 22)               // positivity bias for packed sums
#define M40      ((1ull << 40) - 1ull)

__device__ float        g_partial[BATCH];
__device__ unsigned int g_count = 0;

// Monotone bucket map: quantized value -> [0,511]. Width 2^12 quant units.
__device__ __forceinline__ int bucket_of(int q) {
    int b = (q + (1 << 20)) >> 12;
    return min(max(b, 0), NB - 1);
}

__global__ void __launch_bounds__(THREADS)
distill_fused(const float* __restrict__ y_s,
              const float* __restrict__ y_t,
              const float* __restrict__ w_in,
              float* __restrict__ out, int out_size)
{
    __shared__ unsigned long long s_h[2][NB];   // packed (cnt<<40) + sum(q+KBIAS)
    __shared__ unsigned long long s_p[2][NB];   // exclusive prefix of s_h
    __shared__ int   s_sc[2][NB];               // scatter counters
    __shared__ int   s_stg[2][1024];            // bucket-grouped quantized keys
    __shared__ unsigned long long s_wt64[32];
    __shared__ float s_redA[32], s_redB[32];
    __shared__ float s_ns[2];
    __shared__ float s_fin[2];
    __shared__ bool  s_isLast;

    const int b    = blockIdx.x;
    const int tid  = threadIdx.x;
    const int lane = tid & 31;
    const int wid  = tid >> 5;
    const int hm   = tid >> 9;       // 0/1: which matrix's table this thread services
    const int ht   = tid & (NB - 1); // bucket index serviced

    // ---- phase 0/1: zero tables; load own element into REGISTERS ----
    s_h[hm][ht]  = 0ull;
    s_sc[hm][ht] = 0;

    const bool own = (tid < C);
    float xs = 0.0f, xt = 0.0f, wv = 0.0f;
    if (own) {
        xs = y_s [b * C + tid] * 0.25f;
        xt = y_t [b * C + tid] * 0.25f;
        wv = w_in[b * C + tid];
    }
    const int q0 = __float2int_rn(xs * QSCALE);
    const int q1 = __float2int_rn(xt * QSCALE);
    __syncthreads();

    // ---- phase 2: neg_sum partials + packed histogram build (registers only) ----
    float ns_s = 0.0f, ns_t = 0.0f;
    if (own) {
        float om = 1.0f - wv;
        ns_s = om * __expf(xs);
        ns_t = om * __expf(xt);
        if (wv != 0.0f) {
            atomicAdd(&s_h[0][bucket_of(q0)],
                      (1ull << 40) + (unsigned long long)(unsigned)(q0 + KBIAS));
            atomicAdd(&s_h[1][bucket_of(q1)],
                      (1ull << 40) + (unsigned long long)(unsigned)(q1 + KBIAS));
        }
    }
    #pragma unroll
    for (int d = 16; d > 0; d >>= 1) {
        ns_s += __shfl_down_sync(0xffffffffu, ns_s, d);
        ns_t += __shfl_down_sync(0xffffffffu, ns_t, d);
    }
    if (lane == 0) { s_redA[wid] = ns_s; s_redB[wid] = ns_t; }
    __syncthreads();

    // ---- phase 3: two concurrent exclusive scans (1 bucket per thread) ----
    {
        unsigned long long v    = s_h[hm][ht];
        unsigned long long incl = v;
        #pragma unroll
        for (int d = 1; d < 32; d <<= 1) {
            unsigned long long u = __shfl_up_sync(0xffffffffu, incl, d);
            if (lane >= d) incl += u;
        }
        if (lane == 31) s_wt64[wid] = incl;
        // fold neg_sum combine into warp 1 (parallel with the wait)
        __syncthreads();
        if (tid == 0) {
            unsigned long long run = 0;
            #pragma unroll
            for (int k = 0; k < 16; k++) { unsigned long long tt = s_wt64[k]; s_wt64[k] = run; run += tt; }
        }
        if (tid == 512) {
            unsigned long long run = 0;
            #pragma unroll
            for (int k = 16; k < 32; k++) { unsigned long long tt = s_wt64[k]; s_wt64[k] = run; run += tt; }
        }
        if (tid >= 32 && tid < 64) {
            // warp 1: fixed-tree reduce of the 32 neg_sum partials
            float a  = s_redA[lane];
            float bb = s_redB[lane];
            #pragma unroll
            for (int d = 16; d > 0; d >>= 1) {
                a  += __shfl_down_sync(0xffffffffu, a,  d);
                bb += __shfl_down_sync(0xffffffffu, bb, d);
            }
            if (lane == 0) { s_ns[0] = a; s_ns[1] = bb; }
        }
        __syncthreads();
        s_p[hm][ht] = s_wt64[wid] + (incl - v);
    }
    __syncthreads();

    // ---- phase 4: scatter own keys bucket-grouped (int values: order-free) ----
    if (own && wv != 0.0f) {
        int b0 = bucket_of(q0);
        s_stg[0][(int)(s_p[0][b0] >> 40) + atomicAdd(&s_sc[0][b0], 1)] = q0;
        int b1 = bucket_of(q1);
        s_stg[1][(int)(s_p[1][b1] >> 40) + atomicAdd(&s_sc[1][b1], 1)] = q1;
    }
    __syncthreads();

    // ---- phase 5: own query (both matrices) + epilogue ----
    float contrib = 0.0f;
    if (own) {
        const float negS = s_ns[0];
        const float negT = s_ns[1];

        float t3[2];
        const int qv[2] = { q0, q1 };
        #pragma unroll
        for (int m = 0; m < 2; m++) {
            int q  = qv[m];
            int bk = bucket_of(q);
            unsigned long long pk = s_p[m][bk];
            long long cnt = (long long)(pk >> 40);
            long long sum = (long long)(pk & M40) - (cnt << 22);
            int st = (int)(pk >> 40);
            int n  = (int)(s_h[m][bk] >> 40);
            for (int t = 0; t < n; t++) {
                int kq = s_stg[m][st + t];
                if (kq < q) { cnt++; sum += kq; }
            }
            t3[m] = (float)(cnt * (long long)q - sum) * T3SCALE;
        }

        const float exs = __expf(xs);
        const float ext = __expf(xt);
        const float chs = wv * __expf(-t3[0]) + (1.0f - wv);
        const float cht = wv * __expf(-t3[1]) + (1.0f - wv);

        const float ps = exs / (chs * negS + exs);
        const float pt = ext / (cht * negT + ext);

        const float ps1 = fminf(ps, 1.0f);
        const float pt1 = fminf(pt, 1.0f);

        const float da  = fminf(fabsf((pt1 + 1.0f) * 0.5f - ps1), 1.0f);
        const float pos = wv * sqrtf(sqrtf(da));
        const float neg = (1.0f - wv) * fminf(fabsf(pt1 * 0.5f - ps1), 1.0f);
        const float ept = pos + neg;

        float psE = __expf(ept * __logf(ps1));
        psE = fmaxf(psE, 1e-7f);
        const float ptc = fmaxf(pt, 1e-7f);
        contrib = ptc * __logf(psE);
    }

    // ---- phase 6: block reduction (fixed tree, deterministic) ----
    #pragma unroll
    for (int d = 16; d > 0; d >>= 1)
        contrib += __shfl_down_sync(0xffffffffu, contrib, d);
    if (lane == 0) s_redA[wid] = contrib;
    __syncthreads();

    if (tid < 32) {
        float t = s_redA[lane];
        #pragma unroll
        for (int d = 16; d > 0; d >>= 1)
            t += __shfl_down_sync(0xffffffffu, t, d);
        if (lane == 0) {
            g_partial[b] = t;
            __threadfence();
            unsigned c = atomicAdd(&g_count, 1u);
            s_isLast = (c == (unsigned)(BATCH - 1));
        }
    }
    __syncthreads();

    // ---- phase 7: fused final reduce (last block, fixed order) ----
    if (s_isLast) {
        float v = 0.0f;
        if (tid < BATCH) v = ((volatile float*)g_partial)[tid];
        #pragma unroll
        for (int d = 16; d > 0; d >>= 1)
            v += __shfl_down_sync(0xffffffffu, v, d);
        if (tid == 0)  s_fin[0] = v;
        if (tid == 32) s_fin[1] = v;
        __syncthreads();
        if (tid == 0) {
            // loss = -(total)/B * T^2 = -total * 16/64
            out[0] = -0.25f * (s_fin[0] + s_fin[1]);
            g_count = 0;   // reset for next graph replay
        }
        for (int i = tid; i < out_size; i += THREADS)
            if (i > 0) out[i] = 0.0f;
    }
}

extern "C" void kernel_launch(void* const* d_in, const int* in_sizes, int n_in,
                              void* d_out, int out_size)
{
    const float* y_s = (const float*)d_in[0];
    const float* y_t = (const float*)d_in[1];
    const float* w   = (const float*)d_in[2];

    distill_fused<<<BATCH, THREADS>>>(y_s, y_t, w, (float*)d_out, out_size);
}